// round 1
// baseline (speedup 1.0000x reference)
#include <cuda_runtime.h>
#include <cuda_bf16.h>
#include <math.h>

// Problem constants
#define S        2048
#define DMODEL   2048
#define NHEADS   32
#define NKVHEADS 8
#define HDIM     64
#define KVDIM    (NKVHEADS * HDIM)   // 512

// Scratch buffers (device globals: allocation-free, graph-capturable)
__device__ float g_q[S * DMODEL];     // [s, h*64+d]
__device__ float g_k[S * KVDIM];      // [s, kh*64+d]
__device__ float g_v[S * KVDIM];
__device__ float g_ctx[S * DMODEL];   // [s, h*64+d]

// ---------------------------------------------------------------------------
// Tiled GEMM: C[M,N] = A[M,K] * B[N,K]^T  (+ optional bias over N)
// Both A and B row-major with K contiguous (dot of rows).
// 64x64 tile, BK=32, 256 threads, 4x4 micro-tile per thread.
// ---------------------------------------------------------------------------
__global__ __launch_bounds__(256) void gemm_nt_kernel(
    const float* __restrict__ A, const float* __restrict__ B,
    float* __restrict__ C, int M, int N, int Kdim,
    const float* __restrict__ bias)
{
    __shared__ float As[64][33];
    __shared__ float Bs[64][33];

    const int nb = blockIdx.x;   // N tile
    const int mb = blockIdx.y;   // M tile
    const int tid = threadIdx.x;
    const int ty = tid >> 4;     // 0..15
    const int tx = tid & 15;     // 0..15
    const int r4 = ty * 4;
    const int c4 = tx * 4;

    const float* Ap = A + (size_t)(mb * 64) * Kdim;
    const float* Bp = B + (size_t)(nb * 64) * Kdim;

    float acc[4][4];
#pragma unroll
    for (int i = 0; i < 4; ++i)
#pragma unroll
        for (int j = 0; j < 4; ++j) acc[i][j] = 0.f;

    for (int k0 = 0; k0 < Kdim; k0 += 32) {
        // Load 64x32 tiles of A and B (coalesced: 32 consecutive floats/row)
#pragma unroll
        for (int idx = tid; idx < 64 * 32; idx += 256) {
            int r = idx >> 5;
            int c = idx & 31;
            As[r][c] = Ap[(size_t)r * Kdim + k0 + c];
            Bs[r][c] = Bp[(size_t)r * Kdim + k0 + c];
        }
        __syncthreads();

#pragma unroll
        for (int kk = 0; kk < 32; ++kk) {
            float a0 = As[r4 + 0][kk];
            float a1 = As[r4 + 1][kk];
            float a2 = As[r4 + 2][kk];
            float a3 = As[r4 + 3][kk];
            float b0 = Bs[c4 + 0][kk];
            float b1 = Bs[c4 + 1][kk];
            float b2 = Bs[c4 + 2][kk];
            float b3 = Bs[c4 + 3][kk];
            acc[0][0] += a0 * b0; acc[0][1] += a0 * b1; acc[0][2] += a0 * b2; acc[0][3] += a0 * b3;
            acc[1][0] += a1 * b0; acc[1][1] += a1 * b1; acc[1][2] += a1 * b2; acc[1][3] += a1 * b3;
            acc[2][0] += a2 * b0; acc[2][1] += a2 * b1; acc[2][2] += a2 * b2; acc[2][3] += a2 * b3;
            acc[3][0] += a3 * b0; acc[3][1] += a3 * b1; acc[3][2] += a3 * b2; acc[3][3] += a3 * b3;
        }
        __syncthreads();
    }

#pragma unroll
    for (int i = 0; i < 4; ++i) {
        int row = mb * 64 + r4 + i;
#pragma unroll
        for (int j = 0; j < 4; ++j) {
            int col = nb * 64 + c4 + j;
            float v = acc[i][j];
            if (bias) v += bias[col];
            C[(size_t)row * N + col] = v;
        }
    }
}

// ---------------------------------------------------------------------------
// Causal flash attention, head_dim=64.
// Grid: (S/64 query tiles, NHEADS). 256 threads/CTA.
// Q pre-scaled by 1/sqrt(64). Online softmax, O accumulated in registers.
// ---------------------------------------------------------------------------
__global__ __launch_bounds__(256) void attn_kernel(
    const float* __restrict__ Q, const float* __restrict__ K,
    const float* __restrict__ V, float* __restrict__ CTX)
{
    const int qb = blockIdx.x;      // query tile index
    const int h  = blockIdx.y;      // head
    const int kvh = h >> 2;         // 4 Q heads per KV head

    extern __shared__ float sm[];
    float* Qs  = sm;                 // 64 * 65
    float* Ks  = Qs + 64 * 65;       // 64 * 65
    float* Vs  = Ks + 64 * 65;       // 64 * 65
    float* Ss  = Vs + 64 * 65;       // 64 * 65
    float* m_s = Ss + 64 * 65;       // 64
    float* l_s = m_s + 64;           // 64
    float* a_s = l_s + 64;           // 64

    const int tid = threadIdx.x;
    const int ty = tid >> 4, tx = tid & 15;
    const int r4 = ty * 4, c4 = tx * 4;
    const int srow = tid >> 2;       // softmax: 4 threads per row
    const int slane = tid & 3;

    // Load Q tile (pre-scaled)
    const float* qptr = Q + (size_t)(qb * 64) * DMODEL + h * HDIM;
#pragma unroll
    for (int idx = tid; idx < 64 * 64; idx += 256) {
        int r = idx >> 6, d = idx & 63;
        Qs[r * 65 + d] = qptr[(size_t)r * DMODEL + d] * 0.125f;
    }
    if (tid < 64) { m_s[tid] = -1e30f; l_s[tid] = 0.f; }

    float o[4][4];
#pragma unroll
    for (int i = 0; i < 4; ++i)
#pragma unroll
        for (int j = 0; j < 4; ++j) o[i][j] = 0.f;

    const float* kbase = K + kvh * HDIM;
    const float* vbase = V + kvh * HDIM;

    for (int jb = 0; jb <= qb; ++jb) {
        // Load K,V tiles
#pragma unroll
        for (int idx = tid; idx < 64 * 64; idx += 256) {
            int r = idx >> 6, d = idx & 63;
            size_t g = (size_t)(jb * 64 + r) * KVDIM + d;
            Ks[r * 65 + d] = kbase[g];
            Vs[r * 65 + d] = vbase[g];
        }
        __syncthreads();

        // S tile = Qs * Ks^T (already scaled)
        float sacc[4][4];
#pragma unroll
        for (int i = 0; i < 4; ++i)
#pragma unroll
            for (int j = 0; j < 4; ++j) sacc[i][j] = 0.f;

#pragma unroll 8
        for (int d = 0; d < 64; ++d) {
            float a0 = Qs[(r4 + 0) * 65 + d];
            float a1 = Qs[(r4 + 1) * 65 + d];
            float a2 = Qs[(r4 + 2) * 65 + d];
            float a3 = Qs[(r4 + 3) * 65 + d];
            float b0 = Ks[(c4 + 0) * 65 + d];
            float b1 = Ks[(c4 + 1) * 65 + d];
            float b2 = Ks[(c4 + 2) * 65 + d];
            float b3 = Ks[(c4 + 3) * 65 + d];
            sacc[0][0] += a0 * b0; sacc[0][1] += a0 * b1; sacc[0][2] += a0 * b2; sacc[0][3] += a0 * b3;
            sacc[1][0] += a1 * b0; sacc[1][1] += a1 * b1; sacc[1][2] += a1 * b2; sacc[1][3] += a1 * b3;
            sacc[2][0] += a2 * b0; sacc[2][1] += a2 * b1; sacc[2][2] += a2 * b2; sacc[2][3] += a2 * b3;
            sacc[3][0] += a3 * b0; sacc[3][1] += a3 * b1; sacc[3][2] += a3 * b2; sacc[3][3] += a3 * b3;
        }

        const bool diag = (jb == qb);
#pragma unroll
        for (int i = 0; i < 4; ++i)
#pragma unroll
            for (int j = 0; j < 4; ++j) {
                float sv = sacc[i][j];
                if (diag && (c4 + j) > (r4 + i)) sv = -1e30f;
                Ss[(r4 + i) * 65 + c4 + j] = sv;
            }
        __syncthreads();

        // Online softmax: 4 threads per row
        float mprev = m_s[srow];
        float lmax = -1e30f;
        for (int c = slane; c < 64; c += 4)
            lmax = fmaxf(lmax, Ss[srow * 65 + c]);
        lmax = fmaxf(lmax, __shfl_xor_sync(0xffffffffu, lmax, 1));
        lmax = fmaxf(lmax, __shfl_xor_sync(0xffffffffu, lmax, 2));
        float mnew = fmaxf(mprev, lmax);

        float lsum = 0.f;
        for (int c = slane; c < 64; c += 4) {
            float p = __expf(Ss[srow * 65 + c] - mnew);
            Ss[srow * 65 + c] = p;
            lsum += p;
        }
        lsum += __shfl_xor_sync(0xffffffffu, lsum, 1);
        lsum += __shfl_xor_sync(0xffffffffu, lsum, 2);

        if (slane == 0) {
            float al = __expf(mprev - mnew);
            l_s[srow] = l_s[srow] * al + lsum;
            m_s[srow] = mnew;
            a_s[srow] = al;
        }
        __syncthreads();

        // O = O*alpha + P*V
#pragma unroll
        for (int i = 0; i < 4; ++i) {
            float al = a_s[r4 + i];
            o[i][0] *= al; o[i][1] *= al; o[i][2] *= al; o[i][3] *= al;
        }
#pragma unroll 8
        for (int k = 0; k < 64; ++k) {
            float p0 = Ss[(r4 + 0) * 65 + k];
            float p1 = Ss[(r4 + 1) * 65 + k];
            float p2 = Ss[(r4 + 2) * 65 + k];
            float p3 = Ss[(r4 + 3) * 65 + k];
            float v0 = Vs[k * 65 + c4 + 0];
            float v1 = Vs[k * 65 + c4 + 1];
            float v2 = Vs[k * 65 + c4 + 2];
            float v3 = Vs[k * 65 + c4 + 3];
            o[0][0] += p0 * v0; o[0][1] += p0 * v1; o[0][2] += p0 * v2; o[0][3] += p0 * v3;
            o[1][0] += p1 * v0; o[1][1] += p1 * v1; o[1][2] += p1 * v2; o[1][3] += p1 * v3;
            o[2][0] += p2 * v0; o[2][1] += p2 * v1; o[2][2] += p2 * v2; o[2][3] += p2 * v3;
            o[3][0] += p3 * v0; o[3][1] += p3 * v1; o[3][2] += p3 * v2; o[3][3] += p3 * v3;
        }
        __syncthreads();   // protect smem before next tile load
    }

    // Normalize and write ctx in [s, h*64+d] layout
#pragma unroll
    for (int i = 0; i < 4; ++i) {
        float inv = 1.f / l_s[r4 + i];
        int row = qb * 64 + r4 + i;
#pragma unroll
        for (int j = 0; j < 4; ++j) {
            CTX[(size_t)row * DMODEL + h * HDIM + c4 + j] = o[i][j] * inv;
        }
    }
}

// ---------------------------------------------------------------------------
// Launcher
// ---------------------------------------------------------------------------
extern "C" void kernel_launch(void* const* d_in, const int* in_sizes, int n_in,
                              void* d_out, int out_size)
{
    const float* x   = (const float*)d_in[0];
    // d_in[1] = mask (int32 causal tril) — causality is hardcoded, not read
    const float* w_q = (const float*)d_in[2];
    const float* w_k = (const float*)d_in[3];
    const float* w_v = (const float*)d_in[4];
    const float* w_o = (const float*)d_in[5];
    const float* b_o = (const float*)d_in[6];
    float* out = (float*)d_out;

    float *q, *k, *v, *ctx;
    cudaGetSymbolAddress((void**)&q,   g_q);
    cudaGetSymbolAddress((void**)&k,   g_k);
    cudaGetSymbolAddress((void**)&v,   g_v);
    cudaGetSymbolAddress((void**)&ctx, g_ctx);

    const int ATTN_SMEM = (4 * 64 * 65 + 3 * 64) * (int)sizeof(float);  // 67328 B
    cudaFuncSetAttribute(attn_kernel, cudaFuncAttributeMaxDynamicSharedMemorySize, ATTN_SMEM);

    // Projections: y = x @ W^T
    gemm_nt_kernel<<<dim3(DMODEL / 64, S / 64), 256>>>(x, w_q, q, S, DMODEL, DMODEL, nullptr);
    gemm_nt_kernel<<<dim3(KVDIM  / 64, S / 64), 256>>>(x, w_k, k, S, KVDIM,  DMODEL, nullptr);
    gemm_nt_kernel<<<dim3(KVDIM  / 64, S / 64), 256>>>(x, w_v, v, S, KVDIM,  DMODEL, nullptr);

    // Attention
    attn_kernel<<<dim3(S / 64, NHEADS), 256, ATTN_SMEM>>>(q, k, v, ctx);

    // Output projection + bias
    gemm_nt_kernel<<<dim3(DMODEL / 64, S / 64), 256>>>(ctx, w_o, out, S, DMODEL, DMODEL, b_o);
}

// round 3
// speedup vs baseline: 1.2807x; 1.2807x over previous
#include <cuda_runtime.h>
#include <cuda_bf16.h>
#include <math.h>
#include <cstdint>

// Problem constants
#define S        2048
#define DMODEL   2048
#define NHEADS   32
#define NKVHEADS 8
#define HDIM     64
#define KVDIM    (NKVHEADS * HDIM)   // 512

// ---------------------------------------------------------------------------
// Device-global scratch (allocation-free, graph-capturable)
// ---------------------------------------------------------------------------
__device__ float g_q[S * DMODEL];
__device__ float g_k[S * KVDIM];
__device__ float g_v[S * KVDIM];
__device__ float g_ctx[S * DMODEL];

// bf16 hi/lo splits
__device__ __nv_bfloat16 g_xh[S * DMODEL],       g_xl[S * DMODEL];
__device__ __nv_bfloat16 g_wqh[DMODEL * DMODEL], g_wql[DMODEL * DMODEL];
__device__ __nv_bfloat16 g_wkh[KVDIM * DMODEL],  g_wkl[KVDIM * DMODEL];
__device__ __nv_bfloat16 g_wvh[KVDIM * DMODEL],  g_wvl[KVDIM * DMODEL];
__device__ __nv_bfloat16 g_woh[DMODEL * DMODEL], g_wol[DMODEL * DMODEL];
__device__ __nv_bfloat16 g_ch[S * DMODEL],       g_cl[S * DMODEL];

__device__ __forceinline__ uint32_t smem_u32(const void* p) {
    uint32_t a;
    asm("{ .reg .u64 t; cvta.to.shared.u64 t, %1; cvt.u32.u64 %0, t; }"
        : "=r"(a) : "l"(p));
    return a;
}

// ---------------------------------------------------------------------------
// fp32 -> (hi, lo) bf16 split kernel
// ---------------------------------------------------------------------------
__global__ __launch_bounds__(256) void split_kernel(
    const float* __restrict__ in, __nv_bfloat16* __restrict__ hi,
    __nv_bfloat16* __restrict__ lo, int n4)
{
    int i = blockIdx.x * blockDim.x + threadIdx.x;
    int stride = gridDim.x * blockDim.x;
    const float4* in4 = (const float4*)in;
    __nv_bfloat162* h2 = (__nv_bfloat162*)hi;
    __nv_bfloat162* l2 = (__nv_bfloat162*)lo;
    for (; i < n4; i += stride) {
        float4 v = in4[i];
        __nv_bfloat16 hx = __float2bfloat16_rn(v.x);
        __nv_bfloat16 hy = __float2bfloat16_rn(v.y);
        __nv_bfloat16 hz = __float2bfloat16_rn(v.z);
        __nv_bfloat16 hw = __float2bfloat16_rn(v.w);
        __nv_bfloat16 lx = __float2bfloat16_rn(v.x - __bfloat162float(hx));
        __nv_bfloat16 ly = __float2bfloat16_rn(v.y - __bfloat162float(hy));
        __nv_bfloat16 lz = __float2bfloat16_rn(v.z - __bfloat162float(hz));
        __nv_bfloat16 lw = __float2bfloat16_rn(v.w - __bfloat162float(hw));
        h2[2 * i + 0] = __nv_bfloat162(hx, hy);
        h2[2 * i + 1] = __nv_bfloat162(hz, hw);
        l2[2 * i + 0] = __nv_bfloat162(lx, ly);
        l2[2 * i + 1] = __nv_bfloat162(lz, lw);
    }
}

// ---------------------------------------------------------------------------
// bf16 mma.sync GEMM: C[M,N] = sum_k A[m,k]*B[n,k]  (both K-contiguous)
// 3-term split: Ah*Bh + Al*Bh + Ah*Bl, fp32 accumulate.
// CTA tile 128x128, BK=32, 256 threads (8 warps as 4Mx2N),
// warp tile 32x64 = 2x8 m16n8k16. cp.async double-buffered smem.
// ---------------------------------------------------------------------------
#define BM 128
#define BN 128
#define BK 32
#define PADK 40            // halves per smem row (80 B stride: conflict-free)

__global__ __launch_bounds__(256) void gemm_mma_kernel(
    const __nv_bfloat16* __restrict__ Ah, const __nv_bfloat16* __restrict__ Al,
    const __nv_bfloat16* __restrict__ Bh, const __nv_bfloat16* __restrict__ Bl,
    float* __restrict__ C, int Ktot, int Ncols, const float* __restrict__ bias)
{
    __shared__ __align__(16) __nv_bfloat16 As[2][BM * PADK];
    __shared__ __align__(16) __nv_bfloat16 Bs[2][BN * PADK];

    const int tid   = threadIdx.x;
    const int wid   = tid >> 5;
    const int lane  = tid & 31;
    const int warpM = wid >> 1;     // 0..3
    const int warpN = wid & 1;      // 0..1
    const int g     = lane >> 2;    // 0..7
    const int t     = lane & 3;     // 0..3
    const int mb = blockIdx.y, nb = blockIdx.x;

    const int KT = Ktot / BK;
    const int NT = 3 * KT;
    const size_t rowKb = (size_t)Ktot * 2;   // global row stride in bytes

    float acc[2][8][4];
#pragma unroll
    for (int mt = 0; mt < 2; ++mt)
#pragma unroll
        for (int nt = 0; nt < 8; ++nt)
#pragma unroll
            for (int c = 0; c < 4; ++c) acc[mt][nt][c] = 0.f;

    const uint32_t sA = smem_u32(As);
    const uint32_t sB = smem_u32(Bs);

    auto load_tiles = [&](int kt, int buf) {
        const int seg = kt / KT;
        const int kk  = (kt - seg * KT) * BK;
        const char* aSrc = (const char*)((seg == 1) ? Al : Ah)
                         + (size_t)(mb * BM) * rowKb + (size_t)kk * 2;
        const char* bSrc = (const char*)((seg == 2) ? Bl : Bh)
                         + (size_t)(nb * BN) * rowKb + (size_t)kk * 2;
        const uint32_t sa = sA + buf * (BM * PADK * 2);
        const uint32_t sb = sB + buf * (BN * PADK * 2);
        // 128 rows x 8 chunks of 8B per tile; 256 threads -> 4 chunks each
#pragma unroll
        for (int c = tid; c < BM * 8; c += 256) {
            const int row = c >> 3, col8 = c & 7;
            const uint32_t so = row * (PADK * 2) + col8 * 8;
            const char* ga = aSrc + (size_t)row * rowKb + col8 * 8;
            const char* gb = bSrc + (size_t)row * rowKb + col8 * 8;
            asm volatile("cp.async.ca.shared.global [%0], [%1], 8;"
                         :: "r"(sa + so), "l"(ga));
            asm volatile("cp.async.ca.shared.global [%0], [%1], 8;"
                         :: "r"(sb + so), "l"(gb));
        }
    };

    auto compute = [&](int buf) {
        const uint32_t sa = sA + buf * (BM * PADK * 2)
                          + (warpM * 32 + g) * (PADK * 2) + t * 4;
        const uint32_t sb = sB + buf * (BN * PADK * 2)
                          + (warpN * 64 + g) * (PADK * 2) + t * 4;
#pragma unroll
        for (int ks = 0; ks < 2; ++ks) {
            uint32_t a[2][4];
#pragma unroll
            for (int mt = 0; mt < 2; ++mt) {
                const uint32_t base = sa + mt * 16 * (PADK * 2) + ks * 32;
                asm("ld.shared.b32 %0, [%1];" : "=r"(a[mt][0]) : "r"(base));
                asm("ld.shared.b32 %0, [%1];" : "=r"(a[mt][1]) : "r"(base + 8 * (PADK * 2)));
                asm("ld.shared.b32 %0, [%1];" : "=r"(a[mt][2]) : "r"(base + 16));
                asm("ld.shared.b32 %0, [%1];" : "=r"(a[mt][3]) : "r"(base + 8 * (PADK * 2) + 16));
            }
#pragma unroll
            for (int nt = 0; nt < 8; ++nt) {
                const uint32_t bbase = sb + nt * 8 * (PADK * 2) + ks * 32;
                uint32_t b0, b1;
                asm("ld.shared.b32 %0, [%1];" : "=r"(b0) : "r"(bbase));
                asm("ld.shared.b32 %0, [%1];" : "=r"(b1) : "r"(bbase + 16));
#pragma unroll
                for (int mt = 0; mt < 2; ++mt) {
                    asm volatile(
                        "mma.sync.aligned.m16n8k16.row.col.f32.bf16.bf16.f32 "
                        "{%0,%1,%2,%3}, {%4,%5,%6,%7}, {%8,%9}, {%0,%1,%2,%3};"
                        : "+f"(acc[mt][nt][0]), "+f"(acc[mt][nt][1]),
                          "+f"(acc[mt][nt][2]), "+f"(acc[mt][nt][3])
                        : "r"(a[mt][0]), "r"(a[mt][1]), "r"(a[mt][2]), "r"(a[mt][3]),
                          "r"(b0), "r"(b1));
                }
            }
        }
    };

    // Pipeline: double-buffered cp.async
    load_tiles(0, 0);
    asm volatile("cp.async.commit_group;");

    for (int kt = 0; kt < NT; ++kt) {
        if (kt + 1 < NT) {
            load_tiles(kt + 1, (kt + 1) & 1);
            asm volatile("cp.async.commit_group;");
            asm volatile("cp.async.wait_group 1;");
        } else {
            asm volatile("cp.async.wait_group 0;");
        }
        __syncthreads();
        compute(kt & 1);
        __syncthreads();
    }

    // Epilogue
    const int row0 = mb * BM + warpM * 32 + g;
    const int col0 = nb * BN + warpN * 64 + t * 2;
#pragma unroll
    for (int mt = 0; mt < 2; ++mt) {
#pragma unroll
        for (int nt = 0; nt < 8; ++nt) {
            const int col = col0 + nt * 8;
            float bx = 0.f, by = 0.f;
            if (bias) { bx = bias[col]; by = bias[col + 1]; }
            const int rA = row0 + mt * 16;
            const int rB = rA + 8;
            float2 v0 = make_float2(acc[mt][nt][0] + bx, acc[mt][nt][1] + by);
            float2 v1 = make_float2(acc[mt][nt][2] + bx, acc[mt][nt][3] + by);
            *(float2*)(C + (size_t)rA * Ncols + col) = v0;
            *(float2*)(C + (size_t)rB * Ncols + col) = v1;
        }
    }
}

// ---------------------------------------------------------------------------
// Causal flash attention, head_dim=64 (unchanged from R1, fp32 SIMT).
// ---------------------------------------------------------------------------
__global__ __launch_bounds__(256) void attn_kernel(
    const float* __restrict__ Q, const float* __restrict__ K,
    const float* __restrict__ V, float* __restrict__ CTX)
{
    const int qb = blockIdx.x;
    const int h  = blockIdx.y;
    const int kvh = h >> 2;

    extern __shared__ float sm[];
    float* Qs  = sm;
    float* Ks  = Qs + 64 * 65;
    float* Vs  = Ks + 64 * 65;
    float* Ss  = Vs + 64 * 65;
    float* m_s = Ss + 64 * 65;
    float* l_s = m_s + 64;
    float* a_s = l_s + 64;

    const int tid = threadIdx.x;
    const int ty = tid >> 4, tx = tid & 15;
    const int r4 = ty * 4, c4 = tx * 4;
    const int srow = tid >> 2;
    const int slane = tid & 3;

    const float* qptr = Q + (size_t)(qb * 64) * DMODEL + h * HDIM;
#pragma unroll
    for (int idx = tid; idx < 64 * 64; idx += 256) {
        int r = idx >> 6, d = idx & 63;
        Qs[r * 65 + d] = qptr[(size_t)r * DMODEL + d] * 0.125f;
    }
    if (tid < 64) { m_s[tid] = -1e30f; l_s[tid] = 0.f; }

    float o[4][4];
#pragma unroll
    for (int i = 0; i < 4; ++i)
#pragma unroll
        for (int j = 0; j < 4; ++j) o[i][j] = 0.f;

    const float* kbase = K + kvh * HDIM;
    const float* vbase = V + kvh * HDIM;

    for (int jb = 0; jb <= qb; ++jb) {
#pragma unroll
        for (int idx = tid; idx < 64 * 64; idx += 256) {
            int r = idx >> 6, d = idx & 63;
            size_t gg = (size_t)(jb * 64 + r) * KVDIM + d;
            Ks[r * 65 + d] = kbase[gg];
            Vs[r * 65 + d] = vbase[gg];
        }
        __syncthreads();

        float sacc[4][4];
#pragma unroll
        for (int i = 0; i < 4; ++i)
#pragma unroll
            for (int j = 0; j < 4; ++j) sacc[i][j] = 0.f;

#pragma unroll 8
        for (int d = 0; d < 64; ++d) {
            float a0 = Qs[(r4 + 0) * 65 + d];
            float a1 = Qs[(r4 + 1) * 65 + d];
            float a2 = Qs[(r4 + 2) * 65 + d];
            float a3 = Qs[(r4 + 3) * 65 + d];
            float b0 = Ks[(c4 + 0) * 65 + d];
            float b1 = Ks[(c4 + 1) * 65 + d];
            float b2 = Ks[(c4 + 2) * 65 + d];
            float b3 = Ks[(c4 + 3) * 65 + d];
            sacc[0][0] += a0 * b0; sacc[0][1] += a0 * b1; sacc[0][2] += a0 * b2; sacc[0][3] += a0 * b3;
            sacc[1][0] += a1 * b0; sacc[1][1] += a1 * b1; sacc[1][2] += a1 * b2; sacc[1][3] += a1 * b3;
            sacc[2][0] += a2 * b0; sacc[2][1] += a2 * b1; sacc[2][2] += a2 * b2; sacc[2][3] += a2 * b3;
            sacc[3][0] += a3 * b0; sacc[3][1] += a3 * b1; sacc[3][2] += a3 * b2; sacc[3][3] += a3 * b3;
        }

        const bool diag = (jb == qb);
#pragma unroll
        for (int i = 0; i < 4; ++i)
#pragma unroll
            for (int j = 0; j < 4; ++j) {
                float sv = sacc[i][j];
                if (diag && (c4 + j) > (r4 + i)) sv = -1e30f;
                Ss[(r4 + i) * 65 + c4 + j] = sv;
            }
        __syncthreads();

        float mprev = m_s[srow];
        float lmax = -1e30f;
        for (int c = slane; c < 64; c += 4)
            lmax = fmaxf(lmax, Ss[srow * 65 + c]);
        lmax = fmaxf(lmax, __shfl_xor_sync(0xffffffffu, lmax, 1));
        lmax = fmaxf(lmax, __shfl_xor_sync(0xffffffffu, lmax, 2));
        float mnew = fmaxf(mprev, lmax);

        float lsum = 0.f;
        for (int c = slane; c < 64; c += 4) {
            float p = __expf(Ss[srow * 65 + c] - mnew);
            Ss[srow * 65 + c] = p;
            lsum += p;
        }
        lsum += __shfl_xor_sync(0xffffffffu, lsum, 1);
        lsum += __shfl_xor_sync(0xffffffffu, lsum, 2);

        if (slane == 0) {
            float al = __expf(mprev - mnew);
            l_s[srow] = l_s[srow] * al + lsum;
            m_s[srow] = mnew;
            a_s[srow] = al;
        }
        __syncthreads();

#pragma unroll
        for (int i = 0; i < 4; ++i) {
            float al = a_s[r4 + i];
            o[i][0] *= al; o[i][1] *= al; o[i][2] *= al; o[i][3] *= al;
        }
#pragma unroll 8
        for (int k = 0; k < 64; ++k) {
            float p0 = Ss[(r4 + 0) * 65 + k];
            float p1 = Ss[(r4 + 1) * 65 + k];
            float p2 = Ss[(r4 + 2) * 65 + k];
            float p3 = Ss[(r4 + 3) * 65 + k];
            float v0 = Vs[k * 65 + c4 + 0];
            float v1 = Vs[k * 65 + c4 + 1];
            float v2 = Vs[k * 65 + c4 + 2];
            float v3 = Vs[k * 65 + c4 + 3];
            o[0][0] += p0 * v0; o[0][1] += p0 * v1; o[0][2] += p0 * v2; o[0][3] += p0 * v3;
            o[1][0] += p1 * v0; o[1][1] += p1 * v1; o[1][2] += p1 * v2; o[1][3] += p1 * v3;
            o[2][0] += p2 * v0; o[2][1] += p2 * v1; o[2][2] += p2 * v2; o[2][3] += p2 * v3;
            o[3][0] += p3 * v0; o[3][1] += p3 * v1; o[3][2] += p3 * v2; o[3][3] += p3 * v3;
        }
        __syncthreads();
    }

#pragma unroll
    for (int i = 0; i < 4; ++i) {
        float inv = 1.f / l_s[r4 + i];
        int row = qb * 64 + r4 + i;
#pragma unroll
        for (int j = 0; j < 4; ++j) {
            CTX[(size_t)row * DMODEL + h * HDIM + c4 + j] = o[i][j] * inv;
        }
    }
}

// ---------------------------------------------------------------------------
// Launcher
// ---------------------------------------------------------------------------
extern "C" void kernel_launch(void* const* d_in, const int* in_sizes, int n_in,
                              void* d_out, int out_size)
{
    const float* x   = (const float*)d_in[0];
    // d_in[1] = mask (int32 causal tril) — causality hardcoded
    const float* w_q = (const float*)d_in[2];
    const float* w_k = (const float*)d_in[3];
    const float* w_v = (const float*)d_in[4];
    const float* w_o = (const float*)d_in[5];
    const float* b_o = (const float*)d_in[6];
    float* out = (float*)d_out;

    float *q, *k, *v, *ctx;
    cudaGetSymbolAddress((void**)&q,   g_q);
    cudaGetSymbolAddress((void**)&k,   g_k);
    cudaGetSymbolAddress((void**)&v,   g_v);
    cudaGetSymbolAddress((void**)&ctx, g_ctx);

    __nv_bfloat16 *xh, *xl, *wqh, *wql, *wkh, *wkl, *wvh, *wvl, *woh, *wol, *ch, *cl;
    cudaGetSymbolAddress((void**)&xh,  g_xh);  cudaGetSymbolAddress((void**)&xl,  g_xl);
    cudaGetSymbolAddress((void**)&wqh, g_wqh); cudaGetSymbolAddress((void**)&wql, g_wql);
    cudaGetSymbolAddress((void**)&wkh, g_wkh); cudaGetSymbolAddress((void**)&wkl, g_wkl);
    cudaGetSymbolAddress((void**)&wvh, g_wvh); cudaGetSymbolAddress((void**)&wvl, g_wvl);
    cudaGetSymbolAddress((void**)&woh, g_woh); cudaGetSymbolAddress((void**)&wol, g_wol);
    cudaGetSymbolAddress((void**)&ch,  g_ch);  cudaGetSymbolAddress((void**)&cl,  g_cl);

    const int ATTN_SMEM = (4 * 64 * 65 + 3 * 64) * (int)sizeof(float);
    cudaFuncSetAttribute(attn_kernel, cudaFuncAttributeMaxDynamicSharedMemorySize, ATTN_SMEM);

    // Split inputs to bf16 hi/lo
    split_kernel<<<1024, 256>>>(x,   xh,  xl,  S * DMODEL / 4);
    split_kernel<<<1024, 256>>>(w_q, wqh, wql, DMODEL * DMODEL / 4);
    split_kernel<<<1024, 256>>>(w_k, wkh, wkl, KVDIM * DMODEL / 4);
    split_kernel<<<1024, 256>>>(w_v, wvh, wvl, KVDIM * DMODEL / 4);
    split_kernel<<<1024, 256>>>(w_o, woh, wol, DMODEL * DMODEL / 4);

    // Projections on tensor cores (mma.sync bf16, 3-term split)
    gemm_mma_kernel<<<dim3(DMODEL / BN, S / BM), 256>>>(
        xh, xl, wqh, wql, q, DMODEL, DMODEL, nullptr);
    gemm_mma_kernel<<<dim3(KVDIM / BN, S / BM), 256>>>(
        xh, xl, wkh, wkl, k, DMODEL, KVDIM, nullptr);
    gemm_mma_kernel<<<dim3(KVDIM / BN, S / BM), 256>>>(
        xh, xl, wvh, wvl, v, DMODEL, KVDIM, nullptr);

    // Attention (fp32 SIMT, unchanged)
    attn_kernel<<<dim3(S / 64, NHEADS), 256, ATTN_SMEM>>>(q, k, v, ctx);

    // Output projection + bias
    split_kernel<<<1024, 256>>>(ctx, ch, cl, S * DMODEL / 4);
    gemm_mma_kernel<<<dim3(DMODEL / BN, S / BM), 256>>>(
        ch, cl, woh, wol, out, DMODEL, DMODEL, b_o);
}

// round 4
// speedup vs baseline: 2.0612x; 1.6094x over previous
#include <cuda_runtime.h>
#include <cuda_bf16.h>
#include <math.h>
#include <cstdint>

// Problem constants
#define S        2048
#define DMODEL   2048
#define NHEADS   32
#define NKVHEADS 8
#define HDIM     64
#define KVDIM    (NKVHEADS * HDIM)   // 512

// ---------------------------------------------------------------------------
// Device-global scratch (allocation-free, graph-capturable)
// ---------------------------------------------------------------------------
__device__ __nv_bfloat16 g_xh[S * DMODEL],       g_xl[S * DMODEL];
__device__ __nv_bfloat16 g_wqh[DMODEL * DMODEL], g_wql[DMODEL * DMODEL];
__device__ __nv_bfloat16 g_wkh[KVDIM * DMODEL],  g_wkl[KVDIM * DMODEL];
__device__ __nv_bfloat16 g_wvh[KVDIM * DMODEL],  g_wvl[KVDIM * DMODEL];
__device__ __nv_bfloat16 g_woh[DMODEL * DMODEL], g_wol[DMODEL * DMODEL];
__device__ __nv_bfloat16 g_qh[S * DMODEL],       g_ql[S * DMODEL];
__device__ __nv_bfloat16 g_kh[S * KVDIM],        g_kl[S * KVDIM];
__device__ __nv_bfloat16 g_vh[S * KVDIM],        g_vl[S * KVDIM];
__device__ __nv_bfloat16 g_ch[S * DMODEL],       g_cl[S * DMODEL];

__device__ __forceinline__ uint32_t smem_u32(const void* p) {
    uint32_t a;
    asm("{ .reg .u64 t; cvta.to.shared.u64 t, %1; cvt.u32.u64 %0, t; }"
        : "=r"(a) : "l"(p));
    return a;
}

__device__ __forceinline__ uint32_t pack_bf2(float x, float y) {
    __nv_bfloat162 h = __floats2bfloat162_rn(x, y);
    return *(uint32_t*)&h;
}

#define MMA_BF16(d, a0, a1, a2, a3, b0, b1) \
    asm volatile( \
        "mma.sync.aligned.m16n8k16.row.col.f32.bf16.bf16.f32 " \
        "{%0,%1,%2,%3}, {%4,%5,%6,%7}, {%8,%9}, {%0,%1,%2,%3};" \
        : "+f"((d)[0]), "+f"((d)[1]), "+f"((d)[2]), "+f"((d)[3]) \
        : "r"(a0), "r"(a1), "r"(a2), "r"(a3), "r"(b0), "r"(b1))

#define CP_ASYNC16(dst, src) \
    asm volatile("cp.async.cg.shared.global [%0], [%1], 16;" :: "r"(dst), "l"(src))

// ---------------------------------------------------------------------------
// fp32 -> (hi, lo) bf16 split kernel
// ---------------------------------------------------------------------------
__global__ __launch_bounds__(256) void split_kernel(
    const float* __restrict__ in, __nv_bfloat16* __restrict__ hi,
    __nv_bfloat16* __restrict__ lo, int n4)
{
    int i = blockIdx.x * blockDim.x + threadIdx.x;
    int stride = gridDim.x * blockDim.x;
    const float4* in4 = (const float4*)in;
    __nv_bfloat162* h2 = (__nv_bfloat162*)hi;
    __nv_bfloat162* l2 = (__nv_bfloat162*)lo;
    for (; i < n4; i += stride) {
        float4 v = in4[i];
        __nv_bfloat16 hx = __float2bfloat16_rn(v.x);
        __nv_bfloat16 hy = __float2bfloat16_rn(v.y);
        __nv_bfloat16 hz = __float2bfloat16_rn(v.z);
        __nv_bfloat16 hw = __float2bfloat16_rn(v.w);
        __nv_bfloat16 lx = __float2bfloat16_rn(v.x - __bfloat162float(hx));
        __nv_bfloat16 ly = __float2bfloat16_rn(v.y - __bfloat162float(hy));
        __nv_bfloat16 lz = __float2bfloat16_rn(v.z - __bfloat162float(hz));
        __nv_bfloat16 lw = __float2bfloat16_rn(v.w - __bfloat162float(hw));
        h2[2 * i + 0] = __nv_bfloat162(hx, hy);
        h2[2 * i + 1] = __nv_bfloat162(hz, hw);
        l2[2 * i + 0] = __nv_bfloat162(lx, ly);
        l2[2 * i + 1] = __nv_bfloat162(lz, lw);
    }
}

// ---------------------------------------------------------------------------
// bf16 mma.sync GEMM (3-term split). Epilogue: fp32 (+bias) OR bf16 hi/lo.
// CTA 128x128, BK=32, 256 threads (4Mx2N warps), warp tile 32x64.
// ---------------------------------------------------------------------------
#define BM 128
#define BN 128
#define BK 32
#define PADK 40

__global__ __launch_bounds__(256) void gemm_mma_kernel(
    const __nv_bfloat16* __restrict__ Ah, const __nv_bfloat16* __restrict__ Al,
    const __nv_bfloat16* __restrict__ Bh, const __nv_bfloat16* __restrict__ Bl,
    float* __restrict__ Cf, __nv_bfloat16* __restrict__ Chi,
    __nv_bfloat16* __restrict__ Clo,
    int Ktot, int Ncols, const float* __restrict__ bias, float scale)
{
    __shared__ __align__(16) __nv_bfloat16 As[2][BM * PADK];
    __shared__ __align__(16) __nv_bfloat16 Bs[2][BN * PADK];

    const int tid   = threadIdx.x;
    const int wid   = tid >> 5;
    const int lane  = tid & 31;
    const int warpM = wid >> 1;
    const int warpN = wid & 1;
    const int g     = lane >> 2;
    const int t     = lane & 3;
    const int mb = blockIdx.y, nb = blockIdx.x;

    const int KT = Ktot / BK;
    const int NT = 3 * KT;
    const size_t rowKb = (size_t)Ktot * 2;

    float acc[2][8][4];
#pragma unroll
    for (int mt = 0; mt < 2; ++mt)
#pragma unroll
        for (int nt = 0; nt < 8; ++nt)
#pragma unroll
            for (int c = 0; c < 4; ++c) acc[mt][nt][c] = 0.f;

    const uint32_t sA = smem_u32(As);
    const uint32_t sB = smem_u32(Bs);

    auto load_tiles = [&](int kt, int buf) {
        const int seg = kt / KT;
        const int kk  = (kt - seg * KT) * BK;
        const char* aSrc = (const char*)((seg == 1) ? Al : Ah)
                         + (size_t)(mb * BM) * rowKb + (size_t)kk * 2;
        const char* bSrc = (const char*)((seg == 2) ? Bl : Bh)
                         + (size_t)(nb * BN) * rowKb + (size_t)kk * 2;
        const uint32_t sa = sA + buf * (BM * PADK * 2);
        const uint32_t sb = sB + buf * (BN * PADK * 2);
#pragma unroll
        for (int c = tid; c < BM * 8; c += 256) {
            const int row = c >> 3, col8 = c & 7;
            const uint32_t so = row * (PADK * 2) + col8 * 8;
            const char* ga = aSrc + (size_t)row * rowKb + col8 * 8;
            const char* gb = bSrc + (size_t)row * rowKb + col8 * 8;
            asm volatile("cp.async.ca.shared.global [%0], [%1], 8;"
                         :: "r"(sa + so), "l"(ga));
            asm volatile("cp.async.ca.shared.global [%0], [%1], 8;"
                         :: "r"(sb + so), "l"(gb));
        }
    };

    auto compute = [&](int buf) {
        const uint32_t sa = sA + buf * (BM * PADK * 2)
                          + (warpM * 32 + g) * (PADK * 2) + t * 4;
        const uint32_t sb = sB + buf * (BN * PADK * 2)
                          + (warpN * 64 + g) * (PADK * 2) + t * 4;
#pragma unroll
        for (int ks = 0; ks < 2; ++ks) {
            uint32_t a[2][4];
#pragma unroll
            for (int mt = 0; mt < 2; ++mt) {
                const uint32_t base = sa + mt * 16 * (PADK * 2) + ks * 32;
                asm("ld.shared.b32 %0, [%1];" : "=r"(a[mt][0]) : "r"(base));
                asm("ld.shared.b32 %0, [%1];" : "=r"(a[mt][1]) : "r"(base + 8 * (PADK * 2)));
                asm("ld.shared.b32 %0, [%1];" : "=r"(a[mt][2]) : "r"(base + 16));
                asm("ld.shared.b32 %0, [%1];" : "=r"(a[mt][3]) : "r"(base + 8 * (PADK * 2) + 16));
            }
#pragma unroll
            for (int nt = 0; nt < 8; ++nt) {
                const uint32_t bbase = sb + nt * 8 * (PADK * 2) + ks * 32;
                uint32_t b0, b1;
                asm("ld.shared.b32 %0, [%1];" : "=r"(b0) : "r"(bbase));
                asm("ld.shared.b32 %0, [%1];" : "=r"(b1) : "r"(bbase + 16));
#pragma unroll
                for (int mt = 0; mt < 2; ++mt)
                    MMA_BF16(acc[mt][nt], a[mt][0], a[mt][1], a[mt][2], a[mt][3], b0, b1);
            }
        }
    };

    load_tiles(0, 0);
    asm volatile("cp.async.commit_group;");

    for (int kt = 0; kt < NT; ++kt) {
        if (kt + 1 < NT) {
            load_tiles(kt + 1, (kt + 1) & 1);
            asm volatile("cp.async.commit_group;");
            asm volatile("cp.async.wait_group 1;");
        } else {
            asm volatile("cp.async.wait_group 0;");
        }
        __syncthreads();
        compute(kt & 1);
        __syncthreads();
    }

    const int row0 = mb * BM + warpM * 32 + g;
    const int col0 = nb * BN + warpN * 64 + t * 2;
#pragma unroll
    for (int mt = 0; mt < 2; ++mt) {
#pragma unroll
        for (int nt = 0; nt < 8; ++nt) {
            const int col = col0 + nt * 8;
            const int rA = row0 + mt * 16;
            const int rB = rA + 8;
            float f0 = acc[mt][nt][0] * scale, f1 = acc[mt][nt][1] * scale;
            float f2 = acc[mt][nt][2] * scale, f3 = acc[mt][nt][3] * scale;
            if (Cf) {
                float bx = 0.f, by = 0.f;
                if (bias) { bx = bias[col]; by = bias[col + 1]; }
                *(float2*)(Cf + (size_t)rA * Ncols + col) = make_float2(f0 + bx, f1 + by);
                *(float2*)(Cf + (size_t)rB * Ncols + col) = make_float2(f2 + bx, f3 + by);
            } else {
                __nv_bfloat162 hA = __floats2bfloat162_rn(f0, f1);
                __nv_bfloat162 hB = __floats2bfloat162_rn(f2, f3);
                __nv_bfloat162 lA = __floats2bfloat162_rn(
                    f0 - __bfloat162float(hA.x), f1 - __bfloat162float(hA.y));
                __nv_bfloat162 lB = __floats2bfloat162_rn(
                    f2 - __bfloat162float(hB.x), f3 - __bfloat162float(hB.y));
                *(__nv_bfloat162*)(Chi + (size_t)rA * Ncols + col) = hA;
                *(__nv_bfloat162*)(Chi + (size_t)rB * Ncols + col) = hB;
                *(__nv_bfloat162*)(Clo + (size_t)rA * Ncols + col) = lA;
                *(__nv_bfloat162*)(Clo + (size_t)rB * Ncols + col) = lB;
            }
        }
    }
}

// ---------------------------------------------------------------------------
// Tensor-core causal flash attention.
// BQ=128 per CTA, BKV=64 per iter, 4 warps, 128 threads.
// S = Qh*Kh + Ql*Kh + Qh*Kl ; O += Ph*Vh + Pl*Vh + Ph*Vl (fp32 accum).
// Q pre-scaled by 0.125 at projection. Outputs ctx as bf16 hi/lo.
// ---------------------------------------------------------------------------
#define ATS 72                 // smem row stride in halves (144 B)
#define AT_QBYTES (128 * ATS * 2)     // 18432
#define AT_TBYTES (64 * ATS * 2)      // 9216
#define ATTN_SMEM (2 * AT_QBYTES + 8 * AT_TBYTES)   // 110592

__global__ __launch_bounds__(128) void attn_tc_kernel(
    const __nv_bfloat16* __restrict__ Qh, const __nv_bfloat16* __restrict__ Ql,
    const __nv_bfloat16* __restrict__ Kh, const __nv_bfloat16* __restrict__ Kl,
    const __nv_bfloat16* __restrict__ Vh, const __nv_bfloat16* __restrict__ Vl,
    __nv_bfloat16* __restrict__ Ch, __nv_bfloat16* __restrict__ Cl)
{
    extern __shared__ __align__(16) char smem[];
    const int qb  = (int)gridDim.x - 1 - (int)blockIdx.x;   // big tiles first
    const int h   = blockIdx.y;
    const int kvh = h >> 2;
    const int tid = threadIdx.x, wid = tid >> 5, lane = tid & 31;
    const int g = lane >> 2, t = lane & 3;

    const uint32_t uQh = smem_u32(smem);
    const uint32_t uQl = uQh + AT_QBYTES;
    const uint32_t uKV = uQl + AT_QBYTES;   // [buf][4 tiles: Kh,Kl,Vh,Vl]

    // ---- issue Q loads (once) ----
    {
        const char* srcH = (const char*)(Qh + (size_t)(qb * 128) * DMODEL + h * HDIM);
        const char* srcL = (const char*)(Ql + (size_t)(qb * 128) * DMODEL + h * HDIM);
#pragma unroll
        for (int c = tid; c < 1024; c += 128) {
            const int row = c >> 3, ch = c & 7;
            const uint32_t so = row * 144 + ch * 16;
            const size_t go = (size_t)row * (DMODEL * 2) + ch * 16;
            CP_ASYNC16(uQh + so, srcH + go);
            CP_ASYNC16(uQl + so, srcL + go);
        }
    }

    auto load_kv = [&](int jb, int buf) {
        const __nv_bfloat16* srcs[4] = {Kh, Kl, Vh, Vl};
        const size_t gbase = (size_t)(jb * 64) * KVDIM + kvh * HDIM;
#pragma unroll
        for (int w4 = 0; w4 < 4; ++w4) {
            const char* src = (const char*)(srcs[w4] + gbase);
            const uint32_t dst = uKV + (buf * 4 + w4) * AT_TBYTES;
#pragma unroll
            for (int c = tid; c < 512; c += 128) {
                const int row = c >> 3, ch = c & 7;
                CP_ASYNC16(dst + row * 144 + ch * 16,
                           src + (size_t)row * (KVDIM * 2) + ch * 16);
            }
        }
    };

    load_kv(0, 0);
    asm volatile("cp.async.commit_group;");

    float o[2][8][4];
#pragma unroll
    for (int mt = 0; mt < 2; ++mt)
#pragma unroll
        for (int nt = 0; nt < 8; ++nt)
#pragma unroll
            for (int c = 0; c < 4; ++c) o[mt][nt][c] = 0.f;
    float mst[2][2] = {{-1e30f, -1e30f}, {-1e30f, -1e30f}};
    float lst[2][2] = {{0.f, 0.f}, {0.f, 0.f}};

    const int jbmax = 2 * qb + 1;

    for (int jb = 0; jb <= jbmax; ++jb) {
        const int buf = jb & 1;
        asm volatile("cp.async.wait_group 0;");
        __syncthreads();
        if (jb + 1 <= jbmax) {
            load_kv(jb + 1, buf ^ 1);
            asm volatile("cp.async.commit_group;");
        }

        // ---- S = Q K^T (3-term split) ----
        float s[2][8][4];
#pragma unroll
        for (int mt = 0; mt < 2; ++mt)
#pragma unroll
            for (int nt = 0; nt < 8; ++nt)
#pragma unroll
                for (int c = 0; c < 4; ++c) s[mt][nt][c] = 0.f;

        const uint32_t uKhT = uKV + (buf * 4 + 0) * AT_TBYTES;
        const uint32_t uKlT = uKV + (buf * 4 + 1) * AT_TBYTES;
        const uint32_t uVhT = uKV + (buf * 4 + 2) * AT_TBYTES;
        const uint32_t uVlT = uKV + (buf * 4 + 3) * AT_TBYTES;

#pragma unroll
        for (int ks = 0; ks < 4; ++ks) {
            uint32_t aH[2][4], aL[2][4];
#pragma unroll
            for (int mt = 0; mt < 2; ++mt) {
                const uint32_t bq = (wid * 32 + mt * 16 + g) * 144 + ks * 32 + t * 4;
                asm("ld.shared.b32 %0, [%1];" : "=r"(aH[mt][0]) : "r"(uQh + bq));
                asm("ld.shared.b32 %0, [%1];" : "=r"(aH[mt][1]) : "r"(uQh + bq + 8 * 144));
                asm("ld.shared.b32 %0, [%1];" : "=r"(aH[mt][2]) : "r"(uQh + bq + 16));
                asm("ld.shared.b32 %0, [%1];" : "=r"(aH[mt][3]) : "r"(uQh + bq + 8 * 144 + 16));
                asm("ld.shared.b32 %0, [%1];" : "=r"(aL[mt][0]) : "r"(uQl + bq));
                asm("ld.shared.b32 %0, [%1];" : "=r"(aL[mt][1]) : "r"(uQl + bq + 8 * 144));
                asm("ld.shared.b32 %0, [%1];" : "=r"(aL[mt][2]) : "r"(uQl + bq + 16));
                asm("ld.shared.b32 %0, [%1];" : "=r"(aL[mt][3]) : "r"(uQl + bq + 8 * 144 + 16));
            }
#pragma unroll
            for (int nt = 0; nt < 8; ++nt) {
                const uint32_t bk = (nt * 8 + g) * 144 + ks * 32 + t * 4;
                uint32_t bh0, bh1, bl0, bl1;
                asm("ld.shared.b32 %0, [%1];" : "=r"(bh0) : "r"(uKhT + bk));
                asm("ld.shared.b32 %0, [%1];" : "=r"(bh1) : "r"(uKhT + bk + 16));
                asm("ld.shared.b32 %0, [%1];" : "=r"(bl0) : "r"(uKlT + bk));
                asm("ld.shared.b32 %0, [%1];" : "=r"(bl1) : "r"(uKlT + bk + 16));
#pragma unroll
                for (int mt = 0; mt < 2; ++mt) {
                    MMA_BF16(s[mt][nt], aH[mt][0], aH[mt][1], aH[mt][2], aH[mt][3], bh0, bh1);
                    MMA_BF16(s[mt][nt], aL[mt][0], aL[mt][1], aL[mt][2], aL[mt][3], bh0, bh1);
                    MMA_BF16(s[mt][nt], aH[mt][0], aH[mt][1], aH[mt][2], aH[mt][3], bl0, bl1);
                }
            }
        }

        // ---- causal mask (only needed on the last two kv tiles) ----
        if (jb >= 2 * qb) {
            const int q0 = qb * 128 + wid * 32;
            const int kvb = jb * 64;
#pragma unroll
            for (int mt = 0; mt < 2; ++mt)
#pragma unroll
                for (int nt = 0; nt < 8; ++nt) {
                    const int kv0 = kvb + nt * 8 + 2 * t;
                    const int r0 = q0 + mt * 16 + g;
                    if (kv0 > r0)     s[mt][nt][0] = -1e30f;
                    if (kv0 + 1 > r0) s[mt][nt][1] = -1e30f;
                    if (kv0 > r0 + 8)     s[mt][nt][2] = -1e30f;
                    if (kv0 + 1 > r0 + 8) s[mt][nt][3] = -1e30f;
                }
        }

        // ---- online softmax (per row-slot: (mt, hh)) ----
#pragma unroll
        for (int mt = 0; mt < 2; ++mt)
#pragma unroll
            for (int hh = 0; hh < 2; ++hh) {
                float vmax = -1e30f;
#pragma unroll
                for (int nt = 0; nt < 8; ++nt) {
                    vmax = fmaxf(vmax, fmaxf(s[mt][nt][2 * hh], s[mt][nt][2 * hh + 1]));
                }
                vmax = fmaxf(vmax, __shfl_xor_sync(0xffffffffu, vmax, 1));
                vmax = fmaxf(vmax, __shfl_xor_sync(0xffffffffu, vmax, 2));
                const float mo = mst[mt][hh];
                const float mn = fmaxf(mo, vmax);
                const float corr = __expf(mo - mn);
                float ls = 0.f;
#pragma unroll
                for (int nt = 0; nt < 8; ++nt) {
                    float p0 = __expf(s[mt][nt][2 * hh] - mn);
                    float p1 = __expf(s[mt][nt][2 * hh + 1] - mn);
                    s[mt][nt][2 * hh] = p0;
                    s[mt][nt][2 * hh + 1] = p1;
                    ls += p0 + p1;
                }
                ls += __shfl_xor_sync(0xffffffffu, ls, 1);
                ls += __shfl_xor_sync(0xffffffffu, ls, 2);
                lst[mt][hh] = lst[mt][hh] * corr + ls;
                mst[mt][hh] = mn;
#pragma unroll
                for (int nt = 0; nt < 8; ++nt) {
                    o[mt][nt][2 * hh] *= corr;
                    o[mt][nt][2 * hh + 1] *= corr;
                }
            }

        // ---- convert P to bf16 hi/lo fragments ----
        uint32_t pH[2][8][2], pL[2][8][2];
#pragma unroll
        for (int mt = 0; mt < 2; ++mt)
#pragma unroll
            for (int nt = 0; nt < 8; ++nt) {
                float p0 = s[mt][nt][0], p1 = s[mt][nt][1];
                float p2 = s[mt][nt][2], p3 = s[mt][nt][3];
                __nv_bfloat162 h01 = __floats2bfloat162_rn(p0, p1);
                __nv_bfloat162 h23 = __floats2bfloat162_rn(p2, p3);
                pH[mt][nt][0] = *(uint32_t*)&h01;
                pH[mt][nt][1] = *(uint32_t*)&h23;
                pL[mt][nt][0] = pack_bf2(p0 - __bfloat162float(h01.x),
                                         p1 - __bfloat162float(h01.y));
                pL[mt][nt][1] = pack_bf2(p2 - __bfloat162float(h23.x),
                                         p3 - __bfloat162float(h23.y));
            }

        // ---- O += P V (3-term split), V via ldmatrix.trans ----
        const uint32_t lmrow = lane & 15;
        const uint32_t lmcol = (lane >> 4) * 16;   // bytes
#pragma unroll
        for (int kb = 0; kb < 4; ++kb) {
#pragma unroll
            for (int np = 0; np < 4; ++np) {
                const uint32_t lmoff = (kb * 16 + lmrow) * 144 + np * 32 + lmcol;
                uint32_t vh0, vh1, vh2, vh3, vl0, vl1, vl2, vl3;
                asm volatile("ldmatrix.sync.aligned.m8n8.x4.trans.shared.b16 "
                             "{%0,%1,%2,%3}, [%4];"
                             : "=r"(vh0), "=r"(vh1), "=r"(vh2), "=r"(vh3)
                             : "r"(uVhT + lmoff));
                asm volatile("ldmatrix.sync.aligned.m8n8.x4.trans.shared.b16 "
                             "{%0,%1,%2,%3}, [%4];"
                             : "=r"(vl0), "=r"(vl1), "=r"(vl2), "=r"(vl3)
                             : "r"(uVlT + lmoff));
#pragma unroll
                for (int mt = 0; mt < 2; ++mt) {
                    const uint32_t a0 = pH[mt][2 * kb][0], a1 = pH[mt][2 * kb][1];
                    const uint32_t a2 = pH[mt][2 * kb + 1][0], a3 = pH[mt][2 * kb + 1][1];
                    const uint32_t c0 = pL[mt][2 * kb][0], c1 = pL[mt][2 * kb][1];
                    const uint32_t c2 = pL[mt][2 * kb + 1][0], c3 = pL[mt][2 * kb + 1][1];
                    MMA_BF16(o[mt][2 * np], a0, a1, a2, a3, vh0, vh1);
                    MMA_BF16(o[mt][2 * np], c0, c1, c2, c3, vh0, vh1);
                    MMA_BF16(o[mt][2 * np], a0, a1, a2, a3, vl0, vl1);
                    MMA_BF16(o[mt][2 * np + 1], a0, a1, a2, a3, vh2, vh3);
                    MMA_BF16(o[mt][2 * np + 1], c0, c1, c2, c3, vh2, vh3);
                    MMA_BF16(o[mt][2 * np + 1], a0, a1, a2, a3, vl2, vl3);
                }
            }
        }
        __syncthreads();   // all reads of buf done before next prefetch overwrites
    }

    // ---- epilogue: normalize, write ctx hi/lo ----
#pragma unroll
    for (int mt = 0; mt < 2; ++mt)
#pragma unroll
        for (int hh = 0; hh < 2; ++hh) {
            const float inv = 1.f / lst[mt][hh];
            const int row = qb * 128 + wid * 32 + mt * 16 + hh * 8 + g;
            const size_t gbase = (size_t)row * DMODEL + h * HDIM;
#pragma unroll
            for (int nt = 0; nt < 8; ++nt) {
                const int col = nt * 8 + 2 * t;
                float v0 = o[mt][nt][2 * hh] * inv;
                float v1 = o[mt][nt][2 * hh + 1] * inv;
                __nv_bfloat162 hv = __floats2bfloat162_rn(v0, v1);
                __nv_bfloat162 lv = __floats2bfloat162_rn(
                    v0 - __bfloat162float(hv.x), v1 - __bfloat162float(hv.y));
                *(__nv_bfloat162*)(Ch + gbase + col) = hv;
                *(__nv_bfloat162*)(Cl + gbase + col) = lv;
            }
        }
}

// ---------------------------------------------------------------------------
// Launcher
// ---------------------------------------------------------------------------
extern "C" void kernel_launch(void* const* d_in, const int* in_sizes, int n_in,
                              void* d_out, int out_size)
{
    const float* x   = (const float*)d_in[0];
    // d_in[1] = mask (int32 causal tril) — causality hardcoded
    const float* w_q = (const float*)d_in[2];
    const float* w_k = (const float*)d_in[3];
    const float* w_v = (const float*)d_in[4];
    const float* w_o = (const float*)d_in[5];
    const float* b_o = (const float*)d_in[6];
    float* out = (float*)d_out;

    __nv_bfloat16 *xh, *xl, *wqh, *wql, *wkh, *wkl, *wvh, *wvl, *woh, *wol;
    __nv_bfloat16 *qh, *ql, *kh, *kl, *vh, *vl, *ch, *cl;
    cudaGetSymbolAddress((void**)&xh,  g_xh);  cudaGetSymbolAddress((void**)&xl,  g_xl);
    cudaGetSymbolAddress((void**)&wqh, g_wqh); cudaGetSymbolAddress((void**)&wql, g_wql);
    cudaGetSymbolAddress((void**)&wkh, g_wkh); cudaGetSymbolAddress((void**)&wkl, g_wkl);
    cudaGetSymbolAddress((void**)&wvh, g_wvh); cudaGetSymbolAddress((void**)&wvl, g_wvl);
    cudaGetSymbolAddress((void**)&woh, g_woh); cudaGetSymbolAddress((void**)&wol, g_wol);
    cudaGetSymbolAddress((void**)&qh,  g_qh);  cudaGetSymbolAddress((void**)&ql,  g_ql);
    cudaGetSymbolAddress((void**)&kh,  g_kh);  cudaGetSymbolAddress((void**)&kl,  g_kl);
    cudaGetSymbolAddress((void**)&vh,  g_vh);  cudaGetSymbolAddress((void**)&vl,  g_vl);
    cudaGetSymbolAddress((void**)&ch,  g_ch);  cudaGetSymbolAddress((void**)&cl,  g_cl);

    cudaFuncSetAttribute(attn_tc_kernel, cudaFuncAttributeMaxDynamicSharedMemorySize,
                         ATTN_SMEM);

    // Split inputs to bf16 hi/lo
    split_kernel<<<1024, 256>>>(x,   xh,  xl,  S * DMODEL / 4);
    split_kernel<<<1024, 256>>>(w_q, wqh, wql, DMODEL * DMODEL / 4);
    split_kernel<<<1024, 256>>>(w_k, wkh, wkl, KVDIM * DMODEL / 4);
    split_kernel<<<1024, 256>>>(w_v, wvh, wvl, KVDIM * DMODEL / 4);
    split_kernel<<<1024, 256>>>(w_o, woh, wol, DMODEL * DMODEL / 4);

    // Projections -> bf16 hi/lo outputs (Q pre-scaled by 1/sqrt(64) = 0.125)
    gemm_mma_kernel<<<dim3(DMODEL / BN, S / BM), 256>>>(
        xh, xl, wqh, wql, nullptr, qh, ql, DMODEL, DMODEL, nullptr, 0.125f);
    gemm_mma_kernel<<<dim3(KVDIM / BN, S / BM), 256>>>(
        xh, xl, wkh, wkl, nullptr, kh, kl, DMODEL, KVDIM, nullptr, 1.0f);
    gemm_mma_kernel<<<dim3(KVDIM / BN, S / BM), 256>>>(
        xh, xl, wvh, wvl, nullptr, vh, vl, DMODEL, KVDIM, nullptr, 1.0f);

    // Tensor-core flash attention -> ctx hi/lo
    attn_tc_kernel<<<dim3(S / 128, NHEADS), 128, ATTN_SMEM>>>(
        qh, ql, kh, kl, vh, vl, ch, cl);

    // Output projection + bias (fp32 out)
    gemm_mma_kernel<<<dim3(DMODEL / BN, S / BM), 256>>>(
        ch, cl, woh, wol, out, nullptr, nullptr, DMODEL, DMODEL, b_o, 1.0f);
}

// round 5
// speedup vs baseline: 3.0928x; 1.5005x over previous
#include <cuda_runtime.h>
#include <cuda_bf16.h>
#include <math.h>
#include <cstdint>

// Problem constants
#define S        2048
#define DMODEL   2048
#define NHEADS   32
#define NKVHEADS 8
#define HDIM     64
#define KVDIM    (NKVHEADS * HDIM)   // 512
#define QKV_N    3072                // fused Q(2048) + K(512) + V(512)

// ---------------------------------------------------------------------------
// Device-global scratch (allocation-free, graph-capturable)
// ---------------------------------------------------------------------------
__device__ __nv_bfloat16 g_xh[S * DMODEL],      g_xl[S * DMODEL];
__device__ __nv_bfloat16 g_wh[QKV_N * DMODEL],  g_wl[QKV_N * DMODEL];   // stacked Wq|Wk|Wv
__device__ __nv_bfloat16 g_woh[DMODEL * DMODEL], g_wol[DMODEL * DMODEL];
__device__ __nv_bfloat16 g_qkvh[S * QKV_N],     g_qkvl[S * QKV_N];
__device__ __nv_bfloat16 g_ch[S * DMODEL],      g_cl[S * DMODEL];

__device__ __forceinline__ uint32_t smem_u32(const void* p) {
    uint32_t a;
    asm("{ .reg .u64 t; cvta.to.shared.u64 t, %1; cvt.u32.u64 %0, t; }"
        : "=r"(a) : "l"(p));
    return a;
}

__device__ __forceinline__ uint32_t pack_bf2(float x, float y) {
    __nv_bfloat162 h = __floats2bfloat162_rn(x, y);
    return *(uint32_t*)&h;
}

#define MMA_BF16(d, a0, a1, a2, a3, b0, b1) \
    asm volatile( \
        "mma.sync.aligned.m16n8k16.row.col.f32.bf16.bf16.f32 " \
        "{%0,%1,%2,%3}, {%4,%5,%6,%7}, {%8,%9}, {%0,%1,%2,%3};" \
        : "+f"((d)[0]), "+f"((d)[1]), "+f"((d)[2]), "+f"((d)[3]) \
        : "r"(a0), "r"(a1), "r"(a2), "r"(a3), "r"(b0), "r"(b1))

#define CP_ASYNC16(dst, src) \
    asm volatile("cp.async.cg.shared.global [%0], [%1], 16;" :: "r"(dst), "l"(src))

#define LDSM_X4(r0, r1, r2, r3, addr) \
    asm volatile("ldmatrix.sync.aligned.m8n8.x4.shared.b16 {%0,%1,%2,%3}, [%4];" \
                 : "=r"(r0), "=r"(r1), "=r"(r2), "=r"(r3) : "r"(addr))

// ---------------------------------------------------------------------------
// fp32 -> (hi, lo) bf16 split kernel
// ---------------------------------------------------------------------------
__global__ __launch_bounds__(256) void split_kernel(
    const float* __restrict__ in, __nv_bfloat16* __restrict__ hi,
    __nv_bfloat16* __restrict__ lo, int n4)
{
    int i = blockIdx.x * blockDim.x + threadIdx.x;
    int stride = gridDim.x * blockDim.x;
    const float4* in4 = (const float4*)in;
    __nv_bfloat162* h2 = (__nv_bfloat162*)hi;
    __nv_bfloat162* l2 = (__nv_bfloat162*)lo;
    for (; i < n4; i += stride) {
        float4 v = in4[i];
        __nv_bfloat16 hx = __float2bfloat16_rn(v.x);
        __nv_bfloat16 hy = __float2bfloat16_rn(v.y);
        __nv_bfloat16 hz = __float2bfloat16_rn(v.z);
        __nv_bfloat16 hw = __float2bfloat16_rn(v.w);
        __nv_bfloat16 lx = __float2bfloat16_rn(v.x - __bfloat162float(hx));
        __nv_bfloat16 ly = __float2bfloat16_rn(v.y - __bfloat162float(hy));
        __nv_bfloat16 lz = __float2bfloat16_rn(v.z - __bfloat162float(hz));
        __nv_bfloat16 lw = __float2bfloat16_rn(v.w - __bfloat162float(hw));
        h2[2 * i + 0] = __nv_bfloat162(hx, hy);
        h2[2 * i + 1] = __nv_bfloat162(hz, hw);
        l2[2 * i + 0] = __nv_bfloat162(lx, ly);
        l2[2 * i + 1] = __nv_bfloat162(lz, lw);
    }
}

// ---------------------------------------------------------------------------
// bf16 mma.sync GEMM, 3-term split (Ah*Bh + Al*Bh + Ah*Bl), fp32 accum.
// CTA 128x128, BK=64, 256 threads (4Mx2N warps), warp tile 32x64.
// 3-stage cp.async pipeline, ldmatrix.x4 fragment loads, 1 sync/stage.
// Smem rows: 64 halves + 8 pad = 144 B stride (conflict-free ldmatrix).
// ---------------------------------------------------------------------------
#define BM 128
#define BN 128
#define GSTR 144                     // smem row stride bytes
#define TILE_B (128 * GSTR)          // 18432 per tile
#define STAGE_B (2 * TILE_B)         // A + B per stage
#define GEMM_SMEM (3 * STAGE_B)      // 110592

__global__ __launch_bounds__(256, 2) void gemm_mma_kernel(
    const __nv_bfloat16* __restrict__ Ah, const __nv_bfloat16* __restrict__ Al,
    const __nv_bfloat16* __restrict__ Bh, const __nv_bfloat16* __restrict__ Bl,
    float* __restrict__ Cf, __nv_bfloat16* __restrict__ Chi,
    __nv_bfloat16* __restrict__ Clo,
    int Ktot, int Ncols, const float* __restrict__ bias,
    int qcols, float qscale)
{
    extern __shared__ __align__(16) char smem[];
    const uint32_t sbase = smem_u32(smem);

    const int tid   = threadIdx.x;
    const int lane  = tid & 31;
    const int wid   = tid >> 5;
    const int warpM = wid >> 1;      // 0..3
    const int warpN = wid & 1;       // 0..1
    const int g     = lane >> 2;     // 0..7
    const int t     = lane & 3;      // 0..3
    const int mb = blockIdx.y, nb = blockIdx.x;

    const int KT = Ktot / 64;
    const int NT = 3 * KT;
    const size_t rowKb = (size_t)Ktot * 2;

    float acc[2][8][4];
#pragma unroll
    for (int mt = 0; mt < 2; ++mt)
#pragma unroll
        for (int nt = 0; nt < 8; ++nt)
#pragma unroll
            for (int c = 0; c < 4; ++c) acc[mt][nt][c] = 0.f;

    auto load_stage = [&](int kt, int stg) {
        const int seg = kt / KT;
        const int kk  = (kt - seg * KT) * 64;
        const char* aSrc = (const char*)((seg == 1) ? Al : Ah)
                         + (size_t)(mb * BM) * rowKb + (size_t)kk * 2;
        const char* bSrc = (const char*)((seg == 2) ? Bl : Bh)
                         + (size_t)(nb * BN) * rowKb + (size_t)kk * 2;
        const uint32_t sa = sbase + stg * STAGE_B;
        const uint32_t sb = sa + TILE_B;
#pragma unroll
        for (int c = tid; c < 2048; c += 256) {
            const int row = (c >> 3) & 127;
            const int ch  = c & 7;
            const uint32_t so = row * GSTR + ch * 16;
            if (c < 1024) CP_ASYNC16(sa + so, aSrc + (size_t)row * rowKb + ch * 16);
            else          CP_ASYNC16(sb + so, bSrc + (size_t)row * rowKb + ch * 16);
        }
        asm volatile("cp.async.commit_group;");
    };

    // ldmatrix per-lane address components (byte offsets within a tile)
    const uint32_t aRowOff = (uint32_t)((warpM * 32 + (lane & 15)) * GSTR
                                        + ((lane >> 4) << 4));
    const uint32_t bRowOff = (uint32_t)((warpN * 64 + ((lane >> 4) & 1) * 8 + (lane & 7)) * GSTR
                                        + (((lane >> 3) & 1) << 4));

    auto compute = [&](int stg) {
        const uint32_t aT = sbase + stg * STAGE_B;
        const uint32_t bT = aT + TILE_B;
#pragma unroll
        for (int ks = 0; ks < 4; ++ks) {
            uint32_t a[2][4];
#pragma unroll
            for (int mt = 0; mt < 2; ++mt)
                LDSM_X4(a[mt][0], a[mt][1], a[mt][2], a[mt][3],
                        aT + aRowOff + mt * (16 * GSTR) + ks * 32);
            uint32_t b[8][2];
#pragma unroll
            for (int j = 0; j < 4; ++j) {
                uint32_t r0, r1, r2, r3;
                LDSM_X4(r0, r1, r2, r3, bT + bRowOff + j * (16 * GSTR) + ks * 32);
                b[2 * j][0] = r0; b[2 * j][1] = r1;
                b[2 * j + 1][0] = r2; b[2 * j + 1][1] = r3;
            }
#pragma unroll
            for (int nt = 0; nt < 8; ++nt)
#pragma unroll
                for (int mt = 0; mt < 2; ++mt)
                    MMA_BF16(acc[mt][nt], a[mt][0], a[mt][1], a[mt][2], a[mt][3],
                             b[nt][0], b[nt][1]);
        }
    };

    // 3-stage pipeline
    load_stage(0, 0);
    load_stage(1, 1);

    int stg = 0;
    for (int kt = 0; kt < NT; ++kt) {
        if (kt + 1 < NT) { asm volatile("cp.async.wait_group 1;"); }
        else             { asm volatile("cp.async.wait_group 0;"); }
        __syncthreads();
        if (kt + 2 < NT) {
            int s2 = stg + 2; if (s2 >= 3) s2 -= 3;
            load_stage(kt + 2, s2);
        }
        compute(stg);
        if (++stg == 3) stg = 0;
    }

    // Epilogue
    const int colBase = nb * BN;
    const float sc = (colBase < qcols) ? qscale : 1.0f;
    const int row0 = mb * BM + warpM * 32 + g;
    const int col0 = colBase + warpN * 64 + t * 2;
#pragma unroll
    for (int mt = 0; mt < 2; ++mt) {
#pragma unroll
        for (int nt = 0; nt < 8; ++nt) {
            const int col = col0 + nt * 8;
            const int rA = row0 + mt * 16;
            const int rB = rA + 8;
            float f0 = acc[mt][nt][0] * sc, f1 = acc[mt][nt][1] * sc;
            float f2 = acc[mt][nt][2] * sc, f3 = acc[mt][nt][3] * sc;
            if (Cf) {
                float bx = 0.f, by = 0.f;
                if (bias) { bx = bias[col]; by = bias[col + 1]; }
                *(float2*)(Cf + (size_t)rA * Ncols + col) = make_float2(f0 + bx, f1 + by);
                *(float2*)(Cf + (size_t)rB * Ncols + col) = make_float2(f2 + bx, f3 + by);
            } else {
                __nv_bfloat162 hA = __floats2bfloat162_rn(f0, f1);
                __nv_bfloat162 hB = __floats2bfloat162_rn(f2, f3);
                __nv_bfloat162 lA = __floats2bfloat162_rn(
                    f0 - __bfloat162float(hA.x), f1 - __bfloat162float(hA.y));
                __nv_bfloat162 lB = __floats2bfloat162_rn(
                    f2 - __bfloat162float(hB.x), f3 - __bfloat162float(hB.y));
                *(__nv_bfloat162*)(Chi + (size_t)rA * Ncols + col) = hA;
                *(__nv_bfloat162*)(Chi + (size_t)rB * Ncols + col) = hB;
                *(__nv_bfloat162*)(Clo + (size_t)rA * Ncols + col) = lA;
                *(__nv_bfloat162*)(Clo + (size_t)rB * Ncols + col) = lB;
            }
        }
    }
}

// ---------------------------------------------------------------------------
// Tensor-core causal flash attention (reads fused QKV buffer, stride 3072).
// BQ=128 per CTA, BKV=64 per iter, 4 warps.
// S = Qh*Kh + Ql*Kh + Qh*Kl ; O += Ph*Vh + Pl*Vh + Ph*Vl (fp32 accum).
// ---------------------------------------------------------------------------
#define ATS 72
#define AT_QBYTES (128 * ATS * 2)
#define AT_TBYTES (64 * ATS * 2)
#define ATTN_SMEM (2 * AT_QBYTES + 8 * AT_TBYTES)   // 110592

__global__ __launch_bounds__(128) void attn_tc_kernel(
    const __nv_bfloat16* __restrict__ QKVh, const __nv_bfloat16* __restrict__ QKVl,
    __nv_bfloat16* __restrict__ Ch, __nv_bfloat16* __restrict__ Cl)
{
    extern __shared__ __align__(16) char smem[];
    const int qb  = (int)gridDim.x - 1 - (int)blockIdx.x;
    const int h   = blockIdx.y;
    const int kvh = h >> 2;
    const int tid = threadIdx.x, wid = tid >> 5, lane = tid & 31;
    const int g = lane >> 2, t = lane & 3;

    const uint32_t uQh = smem_u32(smem);
    const uint32_t uQl = uQh + AT_QBYTES;
    const uint32_t uKV = uQl + AT_QBYTES;

    const size_t rowB = QKV_N * 2;   // global row stride bytes

    // Q loads (once)
    {
        const char* srcH = (const char*)(QKVh + (size_t)(qb * 128) * QKV_N + h * HDIM);
        const char* srcL = (const char*)(QKVl + (size_t)(qb * 128) * QKV_N + h * HDIM);
#pragma unroll
        for (int c = tid; c < 1024; c += 128) {
            const int row = c >> 3, ch = c & 7;
            const uint32_t so = row * 144 + ch * 16;
            const size_t go = (size_t)row * rowB + ch * 16;
            CP_ASYNC16(uQh + so, srcH + go);
            CP_ASYNC16(uQl + so, srcL + go);
        }
    }

    const size_t koff = (size_t)DMODEL + kvh * HDIM;
    const size_t voff = (size_t)DMODEL + KVDIM + kvh * HDIM;

    auto load_kv = [&](int jb, int buf) {
        const size_t gbase = (size_t)(jb * 64) * QKV_N;
        const __nv_bfloat16* srcs[4] = {QKVh + gbase + koff, QKVl + gbase + koff,
                                        QKVh + gbase + voff, QKVl + gbase + voff};
#pragma unroll
        for (int w4 = 0; w4 < 4; ++w4) {
            const char* src = (const char*)srcs[w4];
            const uint32_t dst = uKV + (buf * 4 + w4) * AT_TBYTES;
#pragma unroll
            for (int c = tid; c < 512; c += 128) {
                const int row = c >> 3, ch = c & 7;
                CP_ASYNC16(dst + row * 144 + ch * 16,
                           src + (size_t)row * rowB + ch * 16);
            }
        }
    };

    load_kv(0, 0);
    asm volatile("cp.async.commit_group;");

    float o[2][8][4];
#pragma unroll
    for (int mt = 0; mt < 2; ++mt)
#pragma unroll
        for (int nt = 0; nt < 8; ++nt)
#pragma unroll
            for (int c = 0; c < 4; ++c) o[mt][nt][c] = 0.f;
    float mst[2][2] = {{-1e30f, -1e30f}, {-1e30f, -1e30f}};
    float lst[2][2] = {{0.f, 0.f}, {0.f, 0.f}};

    const int jbmax = 2 * qb + 1;

    for (int jb = 0; jb <= jbmax; ++jb) {
        const int buf = jb & 1;
        asm volatile("cp.async.wait_group 0;");
        __syncthreads();
        if (jb + 1 <= jbmax) {
            load_kv(jb + 1, buf ^ 1);
            asm volatile("cp.async.commit_group;");
        }

        float s[2][8][4];
#pragma unroll
        for (int mt = 0; mt < 2; ++mt)
#pragma unroll
            for (int nt = 0; nt < 8; ++nt)
#pragma unroll
                for (int c = 0; c < 4; ++c) s[mt][nt][c] = 0.f;

        const uint32_t uKhT = uKV + (buf * 4 + 0) * AT_TBYTES;
        const uint32_t uKlT = uKV + (buf * 4 + 1) * AT_TBYTES;
        const uint32_t uVhT = uKV + (buf * 4 + 2) * AT_TBYTES;
        const uint32_t uVlT = uKV + (buf * 4 + 3) * AT_TBYTES;

#pragma unroll
        for (int ks = 0; ks < 4; ++ks) {
            uint32_t aH[2][4], aL[2][4];
#pragma unroll
            for (int mt = 0; mt < 2; ++mt) {
                const uint32_t bq = (wid * 32 + mt * 16 + g) * 144 + ks * 32 + t * 4;
                asm("ld.shared.b32 %0, [%1];" : "=r"(aH[mt][0]) : "r"(uQh + bq));
                asm("ld.shared.b32 %0, [%1];" : "=r"(aH[mt][1]) : "r"(uQh + bq + 8 * 144));
                asm("ld.shared.b32 %0, [%1];" : "=r"(aH[mt][2]) : "r"(uQh + bq + 16));
                asm("ld.shared.b32 %0, [%1];" : "=r"(aH[mt][3]) : "r"(uQh + bq + 8 * 144 + 16));
                asm("ld.shared.b32 %0, [%1];" : "=r"(aL[mt][0]) : "r"(uQl + bq));
                asm("ld.shared.b32 %0, [%1];" : "=r"(aL[mt][1]) : "r"(uQl + bq + 8 * 144));
                asm("ld.shared.b32 %0, [%1];" : "=r"(aL[mt][2]) : "r"(uQl + bq + 16));
                asm("ld.shared.b32 %0, [%1];" : "=r"(aL[mt][3]) : "r"(uQl + bq + 8 * 144 + 16));
            }
#pragma unroll
            for (int nt = 0; nt < 8; ++nt) {
                const uint32_t bk = (nt * 8 + g) * 144 + ks * 32 + t * 4;
                uint32_t bh0, bh1, bl0, bl1;
                asm("ld.shared.b32 %0, [%1];" : "=r"(bh0) : "r"(uKhT + bk));
                asm("ld.shared.b32 %0, [%1];" : "=r"(bh1) : "r"(uKhT + bk + 16));
                asm("ld.shared.b32 %0, [%1];" : "=r"(bl0) : "r"(uKlT + bk));
                asm("ld.shared.b32 %0, [%1];" : "=r"(bl1) : "r"(uKlT + bk + 16));
#pragma unroll
                for (int mt = 0; mt < 2; ++mt) {
                    MMA_BF16(s[mt][nt], aH[mt][0], aH[mt][1], aH[mt][2], aH[mt][3], bh0, bh1);
                    MMA_BF16(s[mt][nt], aL[mt][0], aL[mt][1], aL[mt][2], aL[mt][3], bh0, bh1);
                    MMA_BF16(s[mt][nt], aH[mt][0], aH[mt][1], aH[mt][2], aH[mt][3], bl0, bl1);
                }
            }
        }

        if (jb >= 2 * qb) {
            const int q0 = qb * 128 + wid * 32;
            const int kvb = jb * 64;
#pragma unroll
            for (int mt = 0; mt < 2; ++mt)
#pragma unroll
                for (int nt = 0; nt < 8; ++nt) {
                    const int kv0 = kvb + nt * 8 + 2 * t;
                    const int r0 = q0 + mt * 16 + g;
                    if (kv0 > r0)         s[mt][nt][0] = -1e30f;
                    if (kv0 + 1 > r0)     s[mt][nt][1] = -1e30f;
                    if (kv0 > r0 + 8)     s[mt][nt][2] = -1e30f;
                    if (kv0 + 1 > r0 + 8) s[mt][nt][3] = -1e30f;
                }
        }

#pragma unroll
        for (int mt = 0; mt < 2; ++mt)
#pragma unroll
            for (int hh = 0; hh < 2; ++hh) {
                float vmax = -1e30f;
#pragma unroll
                for (int nt = 0; nt < 8; ++nt)
                    vmax = fmaxf(vmax, fmaxf(s[mt][nt][2 * hh], s[mt][nt][2 * hh + 1]));
                vmax = fmaxf(vmax, __shfl_xor_sync(0xffffffffu, vmax, 1));
                vmax = fmaxf(vmax, __shfl_xor_sync(0xffffffffu, vmax, 2));
                const float mo = mst[mt][hh];
                const float mn = fmaxf(mo, vmax);
                const float corr = __expf(mo - mn);
                float ls = 0.f;
#pragma unroll
                for (int nt = 0; nt < 8; ++nt) {
                    float p0 = __expf(s[mt][nt][2 * hh] - mn);
                    float p1 = __expf(s[mt][nt][2 * hh + 1] - mn);
                    s[mt][nt][2 * hh] = p0;
                    s[mt][nt][2 * hh + 1] = p1;
                    ls += p0 + p1;
                }
                ls += __shfl_xor_sync(0xffffffffu, ls, 1);
                ls += __shfl_xor_sync(0xffffffffu, ls, 2);
                lst[mt][hh] = lst[mt][hh] * corr + ls;
                mst[mt][hh] = mn;
#pragma unroll
                for (int nt = 0; nt < 8; ++nt) {
                    o[mt][nt][2 * hh] *= corr;
                    o[mt][nt][2 * hh + 1] *= corr;
                }
            }

        uint32_t pH[2][8][2], pL[2][8][2];
#pragma unroll
        for (int mt = 0; mt < 2; ++mt)
#pragma unroll
            for (int nt = 0; nt < 8; ++nt) {
                float p0 = s[mt][nt][0], p1 = s[mt][nt][1];
                float p2 = s[mt][nt][2], p3 = s[mt][nt][3];
                __nv_bfloat162 h01 = __floats2bfloat162_rn(p0, p1);
                __nv_bfloat162 h23 = __floats2bfloat162_rn(p2, p3);
                pH[mt][nt][0] = *(uint32_t*)&h01;
                pH[mt][nt][1] = *(uint32_t*)&h23;
                pL[mt][nt][0] = pack_bf2(p0 - __bfloat162float(h01.x),
                                         p1 - __bfloat162float(h01.y));
                pL[mt][nt][1] = pack_bf2(p2 - __bfloat162float(h23.x),
                                         p3 - __bfloat162float(h23.y));
            }

        const uint32_t lmrow = lane & 15;
        const uint32_t lmcol = (lane >> 4) * 16;
#pragma unroll
        for (int kb = 0; kb < 4; ++kb) {
#pragma unroll
            for (int np = 0; np < 4; ++np) {
                const uint32_t lmoff = (kb * 16 + lmrow) * 144 + np * 32 + lmcol;
                uint32_t vh0, vh1, vh2, vh3, vl0, vl1, vl2, vl3;
                asm volatile("ldmatrix.sync.aligned.m8n8.x4.trans.shared.b16 "
                             "{%0,%1,%2,%3}, [%4];"
                             : "=r"(vh0), "=r"(vh1), "=r"(vh2), "=r"(vh3)
                             : "r"(uVhT + lmoff));
                asm volatile("ldmatrix.sync.aligned.m8n8.x4.trans.shared.b16 "
                             "{%0,%1,%2,%3}, [%4];"
                             : "=r"(vl0), "=r"(vl1), "=r"(vl2), "=r"(vl3)
                             : "r"(uVlT + lmoff));
#pragma unroll
                for (int mt = 0; mt < 2; ++mt) {
                    const uint32_t a0 = pH[mt][2 * kb][0], a1 = pH[mt][2 * kb][1];
                    const uint32_t a2 = pH[mt][2 * kb + 1][0], a3 = pH[mt][2 * kb + 1][1];
                    const uint32_t c0 = pL[mt][2 * kb][0], c1 = pL[mt][2 * kb][1];
                    const uint32_t c2 = pL[mt][2 * kb + 1][0], c3 = pL[mt][2 * kb + 1][1];
                    MMA_BF16(o[mt][2 * np], a0, a1, a2, a3, vh0, vh1);
                    MMA_BF16(o[mt][2 * np], c0, c1, c2, c3, vh0, vh1);
                    MMA_BF16(o[mt][2 * np], a0, a1, a2, a3, vl0, vl1);
                    MMA_BF16(o[mt][2 * np + 1], a0, a1, a2, a3, vh2, vh3);
                    MMA_BF16(o[mt][2 * np + 1], c0, c1, c2, c3, vh2, vh3);
                    MMA_BF16(o[mt][2 * np + 1], a0, a1, a2, a3, vl2, vl3);
                }
            }
        }
        __syncthreads();
    }

#pragma unroll
    for (int mt = 0; mt < 2; ++mt)
#pragma unroll
        for (int hh = 0; hh < 2; ++hh) {
            const float inv = 1.f / lst[mt][hh];
            const int row = qb * 128 + wid * 32 + mt * 16 + hh * 8 + g;
            const size_t gbase = (size_t)row * DMODEL + h * HDIM;
#pragma unroll
            for (int nt = 0; nt < 8; ++nt) {
                const int col = nt * 8 + 2 * t;
                float v0 = o[mt][nt][2 * hh] * inv;
                float v1 = o[mt][nt][2 * hh + 1] * inv;
                __nv_bfloat162 hv = __floats2bfloat162_rn(v0, v1);
                __nv_bfloat162 lv = __floats2bfloat162_rn(
                    v0 - __bfloat162float(hv.x), v1 - __bfloat162float(hv.y));
                *(__nv_bfloat162*)(Ch + gbase + col) = hv;
                *(__nv_bfloat162*)(Cl + gbase + col) = lv;
            }
        }
}

// ---------------------------------------------------------------------------
// Launcher
// ---------------------------------------------------------------------------
extern "C" void kernel_launch(void* const* d_in, const int* in_sizes, int n_in,
                              void* d_out, int out_size)
{
    const float* x   = (const float*)d_in[0];
    // d_in[1] = mask (int32 causal tril) — causality hardcoded
    const float* w_q = (const float*)d_in[2];
    const float* w_k = (const float*)d_in[3];
    const float* w_v = (const float*)d_in[4];
    const float* w_o = (const float*)d_in[5];
    const float* b_o = (const float*)d_in[6];
    float* out = (float*)d_out;

    __nv_bfloat16 *xh, *xl, *wh, *wl, *woh, *wol, *qkvh, *qkvl, *ch, *cl;
    cudaGetSymbolAddress((void**)&xh,   g_xh);   cudaGetSymbolAddress((void**)&xl,   g_xl);
    cudaGetSymbolAddress((void**)&wh,   g_wh);   cudaGetSymbolAddress((void**)&wl,   g_wl);
    cudaGetSymbolAddress((void**)&woh,  g_woh);  cudaGetSymbolAddress((void**)&wol,  g_wol);
    cudaGetSymbolAddress((void**)&qkvh, g_qkvh); cudaGetSymbolAddress((void**)&qkvl, g_qkvl);
    cudaGetSymbolAddress((void**)&ch,   g_ch);   cudaGetSymbolAddress((void**)&cl,   g_cl);

    cudaFuncSetAttribute(attn_tc_kernel, cudaFuncAttributeMaxDynamicSharedMemorySize,
                         ATTN_SMEM);
    cudaFuncSetAttribute(gemm_mma_kernel, cudaFuncAttributeMaxDynamicSharedMemorySize,
                         GEMM_SMEM);

    // Split inputs to bf16 hi/lo (weights stacked Wq|Wk|Wv)
    split_kernel<<<1024, 256>>>(x,   xh, xl, S * DMODEL / 4);
    split_kernel<<<1024, 256>>>(w_q, wh,                    wl,                    DMODEL * DMODEL / 4);
    split_kernel<<<1024, 256>>>(w_k, wh + DMODEL * DMODEL,  wl + DMODEL * DMODEL,  KVDIM * DMODEL / 4);
    split_kernel<<<1024, 256>>>(w_v, wh + (DMODEL + KVDIM) * DMODEL,
                                      wl + (DMODEL + KVDIM) * DMODEL, KVDIM * DMODEL / 4);
    split_kernel<<<1024, 256>>>(w_o, woh, wol, DMODEL * DMODEL / 4);

    // Fused QKV projection (Q columns scaled by 1/sqrt(64) = 0.125)
    gemm_mma_kernel<<<dim3(QKV_N / BN, S / BM), 256, GEMM_SMEM>>>(
        xh, xl, wh, wl, nullptr, qkvh, qkvl, DMODEL, QKV_N, nullptr,
        DMODEL, 0.125f);

    // Tensor-core flash attention -> ctx hi/lo
    attn_tc_kernel<<<dim3(S / 128, NHEADS), 128, ATTN_SMEM>>>(qkvh, qkvl, ch, cl);

    // Output projection + bias (fp32 out)
    gemm_mma_kernel<<<dim3(DMODEL / BN, S / BM), 256, GEMM_SMEM>>>(
        ch, cl, woh, wol, out, nullptr, nullptr, DMODEL, DMODEL, b_o, 0, 1.0f);
}